// round 3
// baseline (speedup 1.0000x reference)
#include <cuda_runtime.h>
#include <math.h>

#define B_   2
#define N_   4096
#define C_   256
#define NC_  150
#define T_   4
#define HID_ 1024
#define R_   16384   /* T_*N_ */

typedef long long ll;
typedef unsigned long long ull;

/* ---------------- scratch (device globals) ------------------------------- */
__device__ float g_xf  [B_*T_*N_*C_];    /* (B,T*N,C)            */
__device__ float g_clt [B_*NC_*R_];      /* (B,nc,R) k-major     */
__device__ float g_s1  [B_*R_];
__device__ float g_s2  [B_*R_];
__device__ float g_soft[B_*T_*NC_*N_];
__device__ float g_cen [B_*T_*NC_*C_];
__device__ float g_cin [B_*NC_*C_];
__device__ float g_k   [B_*NC_*C_];
__device__ float g_v   [B_*NC_*C_];
__device__ float g_q   [B_*N_*C_];
__device__ float g_attn[B_*N_*C_];
__device__ float g_tmp [B_*N_*C_];
__device__ float g_out1[B_*N_*C_];
__device__ float g_h1  [B_*N_*HID_];
__device__ float g_hg  [B_*N_*HID_];

/* ---------------- f32x2 helpers ------------------------------------------ */
__device__ __forceinline__ ull dup2(float x) {
    unsigned u = __float_as_uint(x);
    return ((ull)u << 32) | (ull)u;
}
__device__ __forceinline__ void ffma2(ull& c, ull a, ull b) {
    asm("fma.rn.f32x2 %0, %1, %2, %0;" : "+l"(c) : "l"(a), "l"(b));
}
__device__ __forceinline__ float2 unpack2(ull v) {
    unsigned lo, hi;
    asm("mov.b64 {%0,%1}, %2;" : "=r"(lo), "=r"(hi) : "l"(v));
    float2 r; r.x = __uint_as_float(lo); r.y = __uint_as_float(hi);
    return r;
}

__device__ __forceinline__ float blockSum256(float v, float* sh) {
    #pragma unroll
    for (int o = 16; o; o >>= 1) v += __shfl_xor_sync(0xffffffffu, v, o);
    if ((threadIdx.x & 31) == 0) sh[threadIdx.x >> 5] = v;
    __syncthreads();
    float r = sh[0]+sh[1]+sh[2]+sh[3]+sh[4]+sh[5]+sh[6]+sh[7];
    __syncthreads();
    return r;
}

__global__ void zero_kernel(float* p, int n) {
    int i = blockIdx.x * 256 + threadIdx.x;
    if (i < n) p[i] = 0.f;
}

/* ---------------- xf = concat(mem, x), float4 ----------------------------- */
__global__ void copy_xf_kernel(const float4* __restrict__ x,
                               const float4* __restrict__ mem,
                               float4* __restrict__ xf) {
    ll i = (ll)blockIdx.x * 256 + threadIdx.x;      /* float4 index, < 2^21 */
    int b  = (int)(i >> 20);
    int rem = (int)(i & 1048575);
    int tt = rem >> 18;
    int rc = rem & 262143;
    float4 v;
    if (tt < 3) v = mem[((ll)(b*3 + tt) << 18) + rc];
    else        v = x[((ll)b << 18) + rc];
    xf[i] = v;
}

/* ---------------- packed-f32x2 SGEMM -------------------------------------
 * C = alpha*(A·op(W) + bias). A:(M,K) rm. TRW=0: W:(N,K). TRW=1: W:(K,N).
 * acc pairs along M. W duplicated in smem. (K/ksplit)%BK==0, lda%4==0.    */
template<int BM, int BN, int TM, int TN, int TRW>
__global__ void gemm2(int M, int N, int K,
                      const float* __restrict__ A, int lda, ll bsA,
                      const float* __restrict__ W, int ldw, ll bsW,
                      float* __restrict__ Cp, ll crs, ll ccs, ll bsC,
                      const float* __restrict__ bias, float alpha, int ksplit) {
    constexpr int BK = 8;
    constexpr int TX = BN / TN, TY = BM / TM, NT = TX * TY;
    __shared__ __align__(16) float As[BK][BM + 2];
    __shared__ __align__(16) ull   Wd[BK][BN + 1];
    int zz = blockIdx.z, bt = zz / ksplit, ks = zz - bt * ksplit;
    A  += (ll)bt * bsA;  W += (ll)bt * bsW;  Cp += (ll)bt * bsC;
    int Kc = K / ksplit;
    int kbeg = ks * Kc, kend = kbeg + Kc;
    int m0 = blockIdx.x * BM, n0 = blockIdx.y * BN;
    int tid = threadIdx.x, tx = tid % TX, ty = tid / TX;
    ull acc[TM/2][TN];
    #pragma unroll
    for (int i = 0; i < TM/2; i++)
        #pragma unroll
        for (int j = 0; j < TN; j++) acc[i][j] = 0ull;

    for (int k0 = kbeg; k0 < kend; k0 += BK) {
        for (int i4 = tid; i4 < BM * (BK/4); i4 += NT) {
            int q = i4 % (BK/4), mm = i4 / (BK/4);
            int m = m0 + mm, k = k0 + q*4;
            float4 v = make_float4(0.f,0.f,0.f,0.f);
            if (m < M) v = *(const float4*)&A[(ll)m * lda + k];
            As[q*4+0][mm] = v.x; As[q*4+1][mm] = v.y;
            As[q*4+2][mm] = v.z; As[q*4+3][mm] = v.w;
        }
        if (TRW == 0) {
            for (int i4 = tid; i4 < BN * (BK/4); i4 += NT) {
                int q = i4 % (BK/4), nn = i4 / (BK/4);
                int n = n0 + nn, k = k0 + q*4;
                float4 v = make_float4(0.f,0.f,0.f,0.f);
                if (n < N) v = *(const float4*)&W[(ll)n * ldw + k];
                Wd[q*4+0][nn] = dup2(v.x); Wd[q*4+1][nn] = dup2(v.y);
                Wd[q*4+2][nn] = dup2(v.z); Wd[q*4+3][nn] = dup2(v.w);
            }
        } else {
            for (int i4 = tid; i4 < (BN/4) * BK; i4 += NT) {
                int q = i4 % (BN/4), kk = i4 / (BN/4);
                int n = n0 + q*4, k = k0 + kk;
                float4 v;
                if (n + 3 < N) v = *(const float4*)&W[(ll)k * ldw + n];
                else {
                    v.x = (n   < N) ? W[(ll)k*ldw + n  ] : 0.f;
                    v.y = (n+1 < N) ? W[(ll)k*ldw + n+1] : 0.f;
                    v.z = (n+2 < N) ? W[(ll)k*ldw + n+2] : 0.f;
                    v.w = (n+3 < N) ? W[(ll)k*ldw + n+3] : 0.f;
                }
                Wd[kk][q*4+0] = dup2(v.x); Wd[kk][q*4+1] = dup2(v.y);
                Wd[kk][q*4+2] = dup2(v.z); Wd[kk][q*4+3] = dup2(v.w);
            }
        }
        __syncthreads();
        #pragma unroll
        for (int kk = 0; kk < BK; kk++) {
            ull ap[TM/2], wp[TN];
            #pragma unroll
            for (int i = 0; i < TM/2; i++)
                ap[i] = *(const ull*)&As[kk][ty*TM + 2*i];
            #pragma unroll
            for (int j = 0; j < TN; j++) wp[j] = Wd[kk][tx*TN + j];
            #pragma unroll
            for (int i = 0; i < TM/2; i++)
                #pragma unroll
                for (int j = 0; j < TN; j++) ffma2(acc[i][j], ap[i], wp[j]);
        }
        __syncthreads();
    }
    #pragma unroll
    for (int i = 0; i < TM/2; i++) {
        int m = m0 + ty*TM + 2*i;
        #pragma unroll
        for (int j = 0; j < TN; j++) {
            int n = n0 + tx*TN + j;
            if (n >= N) continue;
            float2 v = unpack2(acc[i][j]);
            float bb = (bias && ks == 0) ? bias[n] : 0.f;
            if (m < M) {
                float r = (v.x + bb) * alpha;
                float* p = Cp + (ll)m * crs + (ll)n * ccs;
                if (ksplit == 1) *p = r; else atomicAdd(p, r);
            }
            if (m + 1 < M) {
                float r = (v.y + bb) * alpha;
                float* p = Cp + (ll)(m+1) * crs + (ll)n * ccs;
                if (ksplit == 1) *p = r; else atomicAdd(p, r);
            }
        }
    }
}

/* ---------------- cosine scales s1,s2 per (b,r) --------------------------- */
__global__ void scales_kernel(const float* __restrict__ z, const float* __restrict__ clt,
                              const float* __restrict__ p1, const float* __restrict__ p2,
                              float* __restrict__ s1o, float* __restrict__ s2o) {
    __shared__ float p1s[NC_], p2s[NC_], pn[2];
    int b = blockIdx.y;
    int r = blockIdx.x * 256 + threadIdx.x;
    int tid = threadIdx.x;
    if (tid < NC_) { p1s[tid] = p1[tid]; p2s[tid] = p2[tid]; }
    if (tid < 2) {
        const float* p = tid ? p2 : p1;
        float s = 0.f;
        for (int k = 0; k < NC_; k++) s += p[k]*p[k];
        pn[tid] = 1.0f / fmaxf(sqrtf(s), 1e-12f);
    }
    __syncthreads();
    const float* zb = z   + (ll)b * NC_ * R_ + r;
    const float* cb = clt + (ll)b * NC_ * R_ + r;
    float zz = 0.f, zp = 0.f, cc = 0.f, cp = 0.f;
    #pragma unroll 2
    for (int j = 0; j < NC_; j++) {
        float zv = zb[(ll)j * R_];
        float cv = cb[(ll)j * R_];
        zz += zv*zv; zp += zv*p1s[j];
        cc += cv*cv; cp += cv*p2s[j];
    }
    float s1 = zp * pn[0] / fmaxf(sqrtf(zz), 1e-12f);
    float s2 = cp * pn[1] / fmaxf(sqrtf(cc), 1e-12f);
    s1o[(ll)b*R_ + r] = fminf(fmaxf(s1, 0.f), 1.f);
    s2o[(ll)b*R_ + r] = fminf(fmaxf(s2, 0.f), 1.f);
}

/* ---------------- cxz = 0.5*(t1^T@(z*s1) + t2^T@(cl*s2)) ------------------ */
__global__ void cxz_gemm(const float* __restrict__ z, const float* __restrict__ clt,
                         const float* __restrict__ t1, const float* __restrict__ t2,
                         const float* __restrict__ s1, const float* __restrict__ s2,
                         float* __restrict__ out) {
    /* BM=32 (kp), BN=128 (r), BK=8, TM=8, TN=8 -> 64 threads */
    __shared__ __align__(16) float As[8][34];
    __shared__ __align__(16) ull   Wd[8][129];
    int b = blockIdx.z;
    int m0 = blockIdx.x * 32, n0 = blockIdx.y * 128;
    int tid = threadIdx.x, tx = tid % 16, ty = tid / 16;
    const float* zb  = z   + (ll)b * NC_ * R_;
    const float* cb  = clt + (ll)b * NC_ * R_;
    const float* s1b = s1 + (ll)b * R_;
    const float* s2b = s2 + (ll)b * R_;
    ull acc[4][8];
    #pragma unroll
    for (int i = 0; i < 4; i++)
        #pragma unroll
        for (int j = 0; j < 8; j++) acc[i][j] = 0ull;

    for (int k0 = 0; k0 < 300; k0 += 8) {
        for (int i = tid; i < 256; i += 64) {
            int mm = i % 32, kk = i / 32;
            int j = k0 + kk, m = m0 + mm;
            float v = 0.f;
            if (m < NC_) {
                if (j < NC_)        v = t1[j*NC_ + m];
                else if (j < 2*NC_) v = t2[(j-NC_)*NC_ + m];
            }
            As[kk][mm] = v;
        }
        for (int i = tid; i < 256; i += 64) {
            int q = i % 32, kk = i / 32;
            int j = k0 + kk, r = n0 + q*4;
            float4 v = make_float4(0.f,0.f,0.f,0.f);
            float4 s = make_float4(0.f,0.f,0.f,0.f);
            if (j < NC_) {
                v = *(const float4*)&zb[(ll)j * R_ + r];
                s = *(const float4*)&s1b[r];
            } else if (j < 2*NC_) {
                v = *(const float4*)&cb[(ll)(j-NC_) * R_ + r];
                s = *(const float4*)&s2b[r];
            }
            Wd[kk][q*4+0] = dup2(v.x*s.x); Wd[kk][q*4+1] = dup2(v.y*s.y);
            Wd[kk][q*4+2] = dup2(v.z*s.z); Wd[kk][q*4+3] = dup2(v.w*s.w);
        }
        __syncthreads();
        #pragma unroll
        for (int kk = 0; kk < 8; kk++) {
            ull ap[4], wp[8];
            #pragma unroll
            for (int i = 0; i < 4; i++) ap[i] = *(const ull*)&As[kk][ty*8 + 2*i];
            #pragma unroll
            for (int j = 0; j < 8; j++) wp[j] = Wd[kk][tx*8 + j];
            #pragma unroll
            for (int i = 0; i < 4; i++)
                #pragma unroll
                for (int j = 0; j < 8; j++) ffma2(acc[i][j], ap[i], wp[j]);
        }
        __syncthreads();
    }
    #pragma unroll
    for (int i = 0; i < 4; i++) {
        int m = m0 + ty*8 + 2*i;
        #pragma unroll
        for (int j = 0; j < 8; j++) {
            int r = n0 + tx*8 + j;
            float2 v = unpack2(acc[i][j]);
            if (m < NC_)     out[((ll)(b*NC_ + m  )) * R_ + r] = 0.5f * v.x;
            if (m + 1 < NC_) out[((ll)(b*NC_ + m+1)) * R_ + r] = 0.5f * v.y;
        }
    }
}

/* ---------------- softmax + raw copy -------------------------------------- */
__global__ void softmax_rows2(const float* __restrict__ cxz,
                              float* __restrict__ asn, float* __restrict__ soft) {
    int row = blockIdx.x;
    int b = row / 600; int rem = row - b * 600;
    int t = rem / NC_; int k = rem - t * NC_;
    const float* s = cxz + ((ll)(b * NC_ + k)) * R_ + (ll)t * N_;
    ll drow = ((ll)((b * T_ + t) * NC_ + k)) * N_;
    __shared__ float sh[8];
    int tid = threadIdx.x;
    float mx = -1e30f;
    for (int i = tid; i < N_; i += 256) mx = fmaxf(mx, s[i]);
    #pragma unroll
    for (int o = 16; o; o >>= 1) mx = fmaxf(mx, __shfl_xor_sync(0xffffffffu, mx, o));
    if ((tid & 31) == 0) sh[tid >> 5] = mx;
    __syncthreads();
    mx = fmaxf(fmaxf(fmaxf(sh[0],sh[1]),fmaxf(sh[2],sh[3])),
               fmaxf(fmaxf(sh[4],sh[5]),fmaxf(sh[6],sh[7])));
    __syncthreads();
    float sum = 0.f;
    for (int i = tid; i < N_; i += 256) sum += expf(s[i] - mx);
    sum = blockSum256(sum, sh);
    float inv = 1.0f / sum;
    for (int i = tid; i < N_; i += 256) {
        float v = s[i];
        asn[drow + i]  = v;
        soft[drow + i] = expf(v - mx) * inv;
    }
}

/* ---------------- gate + LayerNorm --------------------------------------- */
__global__ void gate_ln_kernel(const float* __restrict__ cen,
                               const float* __restrict__ nw, const float* __restrict__ nb,
                               const float* __restrict__ salpha, const float* __restrict__ sbeta,
                               float* __restrict__ cin_out) {
    int k = blockIdx.x, b = blockIdx.y, c = threadIdx.x;
    __shared__ float sh[8];
    float pv[4];
    #pragma unroll
    for (int t = 0; t < 4; t++)
        pv[t] = cen[(((ll)b*4 + t) * NC_ + k) * C_ + c];
    float last = pv[3];
    float ll2 = blockSum256(last*last, sh);
    float cin = last;
    float alpha = salpha[0], beta = sbeta[0];
    for (int t = 0; t < 3; t++) {
        float dt = blockSum256(last * pv[t], sh);
        float pp = blockSum256(pv[t] * pv[t], sh);
        float denom = fmaxf(sqrtf(ll2) * sqrtf(pp), 1e-8f);
        float gate = 1.0f / (1.0f + expf(-(beta + alpha * (dt / denom))));
        cin += gate * pv[t];
    }
    float m  = blockSum256(cin, sh) * (1.0f / C_);
    float dv = cin - m;
    float var = blockSum256(dv*dv, sh) * (1.0f / C_);
    cin_out[((ll)b*NC_ + k) * C_ + c] = dv * rsqrtf(var + 1e-5f) * nw[c] + nb[c];
}

/* ---------------- K/V projections ---------------------------------------- */
__global__ void kv_kernel(const float* __restrict__ cin,
                          const float* __restrict__ kw, const float* __restrict__ kb,
                          const float* __restrict__ vw, const float* __restrict__ vb,
                          float* __restrict__ ko, float* __restrict__ vo) {
    int row = blockIdx.x, c = threadIdx.x;
    __shared__ float ci[C_];
    ci[c] = cin[(ll)row * C_ + c];
    __syncthreads();
    float ka = kb[c], va = vb[c];
    const float* kwr = kw + (ll)c * C_;
    const float* vwr = vw + (ll)c * C_;
    #pragma unroll 4
    for (int j = 0; j < C_; j++) {
        float cv = ci[j];
        ka += cv * kwr[j];
        va += cv * vwr[j];
    }
    ko[(ll)row * C_ + c] = ka;
    vo[(ll)row * C_ + c] = va;
}

/* ---------------- fused attention (8 queries/block) ----------------------- */
__global__ void attn_kernel(const float* __restrict__ q, const float* __restrict__ ks,
                            const float* __restrict__ vs, float* __restrict__ o) {
    const int b = blockIdx.y;
    const int n0 = blockIdx.x * 8;
    __shared__ float qs[8][C_];
    __shared__ float P[8][8][152];
    int tid = threadIdx.x;
    for (int i = tid; i < 8*C_; i += 256)
        qs[i >> 8][i & 255] = q[((ll)b*N_ + n0 + (i >> 8)) * C_ + (i & 255)];
    __syncthreads();
    int h = tid >> 5, lane = tid & 31;
    float lg[8][5];
    #pragma unroll
    for (int g = 0; g < 8; g++)
        #pragma unroll
        for (int s = 0; s < 5; s++) lg[g][s] = -1e30f;
    #pragma unroll
    for (int s = 0; s < 5; s++) {
        int idx = lane + s*32;
        if (idx < NC_) {
            const float4* kp = reinterpret_cast<const float4*>(ks + ((ll)b*NC_ + idx)*C_ + h*32);
            float4 kk[8];
            #pragma unroll
            for (int u = 0; u < 8; u++) kk[u] = kp[u];
            #pragma unroll
            for (int g = 0; g < 8; g++) {
                const float* qb = &qs[g][h*32];
                float d = 0.f;
                #pragma unroll
                for (int u = 0; u < 8; u++)
                    d += kk[u].x*qb[u*4] + kk[u].y*qb[u*4+1] + kk[u].z*qb[u*4+2] + kk[u].w*qb[u*4+3];
                lg[g][s] = d;
            }
        }
    }
    float invg[8];
    #pragma unroll
    for (int g = 0; g < 8; g++) {
        float mx = -1e30f;
        #pragma unroll
        for (int s = 0; s < 5; s++) mx = fmaxf(mx, lg[g][s]);
        #pragma unroll
        for (int o2 = 16; o2; o2 >>= 1) mx = fmaxf(mx, __shfl_xor_sync(0xffffffffu, mx, o2));
        float sum = 0.f;
        #pragma unroll
        for (int s = 0; s < 5; s++) {
            int idx = lane + s*32;
            if (idx < NC_) {
                float e = expf(lg[g][s] - mx);
                P[h][g][idx] = e;
                sum += e;
            }
        }
        #pragma unroll
        for (int o2 = 16; o2; o2 >>= 1) sum += __shfl_xor_sync(0xffffffffu, sum, o2);
        invg[g] = 1.0f / sum;
    }
    __syncwarp();
    float og[8] = {0.f,0.f,0.f,0.f,0.f,0.f,0.f,0.f};
    for (int j = 0; j < NC_; j++) {
        float vv = vs[((ll)b*NC_ + j) * C_ + h*32 + lane];
        #pragma unroll
        for (int g = 0; g < 8; g++) og[g] += P[h][g][j] * vv;
    }
    #pragma unroll
    for (int g = 0; g < 8; g++)
        o[((ll)b*N_ + n0 + g) * C_ + h*32 + lane] = og[g] * invg[g];
}

/* ---------------- smem-tiled depthwise 3x3 conv + GELU -------------------- */
__global__ void conv_gelu2(const float* __restrict__ h,
                           const float* __restrict__ dww, const float* __restrict__ dwb,
                           float* __restrict__ out) {
    __shared__ float patch[10][10][64];
    int ch0 = blockIdx.x * 64;
    int tileid = blockIdx.y;
    int y0 = (tileid >> 3) * 8, x0 = (tileid & 7) * 8;
    int b = blockIdx.z;
    int tid = threadIdx.x;
    for (int i = tid; i < 6400; i += 256) {
        int c = i & 63, sp = i >> 6;
        int py = sp / 10, px = sp % 10;
        int yy = y0 + py - 1, xx = x0 + px - 1;
        float v = 0.f;
        if (yy >= 0 && yy < 64 && xx >= 0 && xx < 64)
            v = h[(((ll)b*N_) + (yy*64 + xx)) * HID_ + ch0 + c];
        patch[py][px][c] = v;
    }
    __syncthreads();
    int c = tid & 63, sub = tid >> 6;
    float w[9];
    #pragma unroll
    for (int i = 0; i < 9; i++) w[i] = dww[(ch0 + c)*9 + i];
    float bv = dwb[ch0 + c];
    for (int oy = sub; oy < 8; oy += 4) {
        #pragma unroll
        for (int ox = 0; ox < 8; ox++) {
            float a = bv;
            #pragma unroll
            for (int dy = 0; dy < 3; dy++)
                #pragma unroll
                for (int dx = 0; dx < 3; dx++)
                    a += patch[oy+dy][ox+dx][c] * w[dy*3+dx];
            float g = 0.5f * a * (1.0f + erff(a * 0.7071067811865475f));
            out[(((ll)b*N_) + ((y0+oy)*64 + x0+ox)) * HID_ + ch0 + c] = g;
        }
    }
}

/* ---------------- residual + LayerNorm ------------------------------------ */
__global__ void add_ln_kernel(const float* __restrict__ res, const float* __restrict__ val,
                              const float* __restrict__ nw, const float* __restrict__ nb,
                              float* __restrict__ dst) {
    ll row = blockIdx.x;
    int c = threadIdx.x;
    __shared__ float sh[8];
    float v = val[row * C_ + c];
    float m = blockSum256(v, sh) * (1.0f / C_);
    float d = v - m;
    float var = blockSum256(d*d, sh) * (1.0f / C_);
    dst[row * C_ + c] = res[row * C_ + c] + d * rsqrtf(var + 1e-5f) * nw[c] + nb[c];
}

/* ---------------- host launch --------------------------------------------- */
static float* symaddr(const void* sym) {
    void* p = nullptr;
    cudaGetSymbolAddress(&p, sym);
    return (float*)p;
}

extern "C" void kernel_launch(void* const* d_in, const int* in_sizes, int n_in,
                              void* d_out, int out_size) {
    const float* x    = (const float*)d_in[0];
    const float* z    = (const float*)d_in[1];
    const float* mem  = (const float*)d_in[2];
    const float* cw   = (const float*)d_in[3];
    const float* p1   = (const float*)d_in[4];
    const float* t1   = (const float*)d_in[5];
    const float* p2   = (const float*)d_in[6];
    const float* t2   = (const float*)d_in[7];
    const float* sal  = (const float*)d_in[8];
    const float* sbe  = (const float*)d_in[9];
    const float* qw   = (const float*)d_in[10];
    const float* qb   = (const float*)d_in[11];
    const float* kw   = (const float*)d_in[12];
    const float* kb   = (const float*)d_in[13];
    const float* vw   = (const float*)d_in[14];
    const float* vb   = (const float*)d_in[15];
    const float* pw   = (const float*)d_in[16];
    const float* pb   = (const float*)d_in[17];
    const float* nw   = (const float*)d_in[18];
    const float* nb   = (const float*)d_in[19];
    const float* f1w  = (const float*)d_in[20];
    const float* f1b  = (const float*)d_in[21];
    const float* dww  = (const float*)d_in[22];
    const float* dwb  = (const float*)d_in[23];
    const float* f2w  = (const float*)d_in[24];
    const float* f2b  = (const float*)d_in[25];

    float* out_main = (float*)d_out;
    float* out_cxz  = out_main + (ll)B_*N_*C_;
    float* out_asn  = out_cxz  + (ll)B_*NC_*R_;

    float* xf   = symaddr(g_xf);
    float* clt  = symaddr(g_clt);
    float* s1   = symaddr(g_s1);
    float* s2   = symaddr(g_s2);
    float* soft = symaddr(g_soft);
    float* cen  = symaddr(g_cen);
    float* cin  = symaddr(g_cin);
    float* ksc  = symaddr(g_k);
    float* vsc  = symaddr(g_v);
    float* qsc  = symaddr(g_q);
    float* atn  = symaddr(g_attn);
    float* tmp  = symaddr(g_tmp);
    float* out1 = symaddr(g_out1);
    float* h1   = symaddr(g_h1);
    float* hg   = symaddr(g_hg);

    /* 1. xf = concat(mem, x) */
    copy_xf_kernel<<<8192, 256>>>((const float4*)x, (const float4*)mem, (float4*)xf);

    /* 2. clt[b,k,r] = xf[b,r,:]·cw[k,:]  (transposed store) */
    gemm2<128,32,8,4,0><<<dim3(R_/128, 5, B_), 128>>>(
        R_, NC_, C_, xf, C_, (ll)R_*C_, cw, C_, 0,
        clt, 1, R_, (ll)NC_*R_, nullptr, 1.0f, 1);

    /* 3. cosine scales */
    scales_kernel<<<dim3(R_/256, B_), 256>>>(z, clt, p1, p2, s1, s2);

    /* 4. cluster_x_z */
    cxz_gemm<<<dim3(5, R_/128, B_), 64>>>(z, clt, t1, t2, s1, s2, out_cxz);

    /* 5. softmax + assigned copy */
    softmax_rows2<<<B_*T_*NC_, 256>>>(out_cxz, out_asn, soft);

    /* 6. cen = soft @ xf  (split-K=8, atomic) */
    zero_kernel<<<(B_*T_*NC_*C_ + 255)/256, 256>>>(cen, B_*T_*NC_*C_);
    gemm2<32,64,4,8,1><<<dim3(5, 4, B_*T_*8), 64>>>(
        NC_, C_, N_, soft, N_, (ll)NC_*N_, xf, C_, (ll)N_*C_,
        cen, C_, 1, (ll)NC_*C_, nullptr, 1.0f, 8);

    /* 7. gate + LN */
    gate_ln_kernel<<<dim3(NC_, B_), 256>>>(cen, nw, nb, sal, sbe, cin);

    /* 8. k,v */
    kv_kernel<<<B_*NC_, 256>>>(cin, kw, kb, vw, vb, ksc, vsc);

    /* 9. q */
    gemm2<64,128,8,8,0><<<dim3(B_*N_/64, 2, 1), 128>>>(
        B_*N_, C_, C_, x, C_, 0, qw, C_, 0,
        qsc, C_, 1, 0, qb, 0.17677669529663687f, 1);

    /* 10. attention */
    attn_kernel<<<dim3(N_/8, B_), 256>>>(qsc, ksc, vsc, atn);

    /* 11. proj */
    gemm2<64,128,8,8,0><<<dim3(B_*N_/64, 2, 1), 128>>>(
        B_*N_, C_, C_, atn, C_, 0, pw, C_, 0,
        tmp, C_, 1, 0, pb, 1.0f, 1);

    /* 12. out1 = x + LN(proj) */
    add_ln_kernel<<<B_*N_, 256>>>(x, tmp, nw, nb, out1);

    /* 13. fc1 */
    gemm2<64,128,8,8,0><<<dim3(B_*N_/64, 8, 1), 128>>>(
        B_*N_, HID_, C_, out1, C_, 0, f1w, C_, 0,
        h1, HID_, 1, 0, f1b, 1.0f, 1);

    /* 14. depthwise conv + GELU (smem-tiled) */
    conv_gelu2<<<dim3(HID_/64, 64, B_), 256>>>(h1, dww, dwb, hg);

    /* 15. fc2 */
    gemm2<64,128,8,8,0><<<dim3(B_*N_/64, 2, 1), 128>>>(
        B_*N_, C_, HID_, hg, HID_, 0, f2w, HID_, 0,
        tmp, C_, 1, 0, f2b, 1.0f, 1);

    /* 16. out = out1 + LN(fc2) */
    add_ln_kernel<<<B_*N_, 256>>>(out1, tmp, nw, nb, out_main);
}

// round 4
// speedup vs baseline: 1.9698x; 1.9698x over previous
#include <cuda_runtime.h>
#include <math.h>

#define B_   2
#define N_   4096
#define C_   256
#define NC_  150
#define T_   4
#define HID_ 1024
#define R_   16384   /* T_*N_ */

typedef long long ll;

/* ---------------- scratch (device globals) ------------------------------- */
__device__ float g_xf  [B_*T_*N_*C_];
__device__ float g_clt [B_*NC_*R_];      /* (B,nc,R) k-major */
__device__ float g_s1  [B_*R_];
__device__ float g_s2  [B_*R_];
__device__ float g_soft[B_*T_*NC_*N_];
__device__ float g_cen [B_*T_*NC_*C_];
__device__ float g_cin [B_*NC_*C_];
__device__ float g_k   [B_*NC_*C_];
__device__ float g_v   [B_*NC_*C_];
__device__ float g_q   [B_*N_*C_];
__device__ float g_attn[B_*N_*C_];
__device__ float g_tmp [B_*N_*C_];
__device__ float g_out1[B_*N_*C_];
__device__ float g_h1  [B_*N_*HID_];
__device__ float g_hg  [B_*N_*HID_];

__device__ __forceinline__ float blockSum256(float v, float* sh) {
    #pragma unroll
    for (int o = 16; o; o >>= 1) v += __shfl_xor_sync(0xffffffffu, v, o);
    if ((threadIdx.x & 31) == 0) sh[threadIdx.x >> 5] = v;
    __syncthreads();
    float r = sh[0]+sh[1]+sh[2]+sh[3]+sh[4]+sh[5]+sh[6]+sh[7];
    __syncthreads();
    return r;
}

__global__ void zero_kernel(float* p, int n) {
    int i = blockIdx.x * 256 + threadIdx.x;
    if (i < n) p[i] = 0.f;
}

/* ---------------- xf = concat(mem, x), float4 ----------------------------- */
__global__ void copy_xf_kernel(const float4* __restrict__ x,
                               const float4* __restrict__ mem,
                               float4* __restrict__ xf) {
    ll i = (ll)blockIdx.x * 256 + threadIdx.x;
    int b  = (int)(i >> 20);
    int rem = (int)(i & 1048575);
    int tt = rem >> 18;
    int rc = rem & 262143;
    float4 v;
    if (tt < 3) v = mem[((ll)(b*3 + tt) << 18) + rc];
    else        v = x[((ll)b << 18) + rc];
    xf[i] = v;
}

/* ---------------- scalar SGEMM with float4 loads --------------------------
 * C = alpha*(A·op(W) + bias). A:(M,K) rm. transW=0: W:(N,K). 1: W:(K,N).
 * Requires lda%4==0, (K/ksplit)%8==0, TM%4==0, TN%4==0.                   */
template<int BM, int BN, int TM, int TN>
__global__ void gemm_t(int M, int N, int K,
                       const float* __restrict__ A, int lda, ll bsA,
                       const float* __restrict__ W, int ldw, ll bsW, int transW,
                       float* __restrict__ Cp, ll crs, ll ccs, ll bsC,
                       const float* __restrict__ bias, float alpha, int ksplit) {
    constexpr int BK = 8;
    constexpr int TX = BN / TN, TY = BM / TM, NT = TX * TY;
    __shared__ __align__(16) float As[BK][BM + 4];
    __shared__ __align__(16) float Ws[BK][BN + 4];
    int zz = blockIdx.z, bt = zz / ksplit, ks = zz - bt * ksplit;
    A  += (ll)bt * bsA;  W += (ll)bt * bsW;  Cp += (ll)bt * bsC;
    int Kc = K / ksplit;
    int kbeg = ks * Kc, kend = kbeg + Kc;
    int m0 = blockIdx.x * BM, n0 = blockIdx.y * BN;
    int tid = threadIdx.x, tx = tid % TX, ty = tid / TX;
    float acc[TM][TN];
    #pragma unroll
    for (int i = 0; i < TM; i++)
        #pragma unroll
        for (int j = 0; j < TN; j++) acc[i][j] = 0.f;

    for (int k0 = kbeg; k0 < kend; k0 += BK) {
        for (int i4 = tid; i4 < BM * (BK/4); i4 += NT) {
            int q = i4 % (BK/4), mm = i4 / (BK/4);
            int m = m0 + mm, k = k0 + q*4;
            float4 v = make_float4(0.f,0.f,0.f,0.f);
            if (m < M && k < kend) v = *(const float4*)&A[(ll)m * lda + k];
            As[q*4+0][mm] = v.x; As[q*4+1][mm] = v.y;
            As[q*4+2][mm] = v.z; As[q*4+3][mm] = v.w;
        }
        if (!transW) {
            for (int i4 = tid; i4 < BN * (BK/4); i4 += NT) {
                int q = i4 % (BK/4), nn = i4 / (BK/4);
                int n = n0 + nn, k = k0 + q*4;
                float4 v = make_float4(0.f,0.f,0.f,0.f);
                if (n < N && k < kend) v = *(const float4*)&W[(ll)n * ldw + k];
                Ws[q*4+0][nn] = v.x; Ws[q*4+1][nn] = v.y;
                Ws[q*4+2][nn] = v.z; Ws[q*4+3][nn] = v.w;
            }
        } else {
            for (int i4 = tid; i4 < (BN/4) * BK; i4 += NT) {
                int q = i4 % (BN/4), kk = i4 / (BN/4);
                int n = n0 + q*4, k = k0 + kk;
                float4 v = make_float4(0.f,0.f,0.f,0.f);
                if (k < kend) {
                    if (n + 3 < N) v = *(const float4*)&W[(ll)k * ldw + n];
                    else {
                        v.x = (n   < N) ? W[(ll)k*ldw + n  ] : 0.f;
                        v.y = (n+1 < N) ? W[(ll)k*ldw + n+1] : 0.f;
                        v.z = (n+2 < N) ? W[(ll)k*ldw + n+2] : 0.f;
                        v.w = (n+3 < N) ? W[(ll)k*ldw + n+3] : 0.f;
                    }
                }
                *(float4*)&Ws[kk][q*4] = v;
            }
        }
        __syncthreads();
        #pragma unroll
        for (int kk = 0; kk < BK; kk++) {
            float a[TM], w[TN];
            #pragma unroll
            for (int i = 0; i < TM/4; i++)
                *(float4*)&a[i*4] = *(const float4*)&As[kk][ty*TM + i*4];
            #pragma unroll
            for (int j = 0; j < TN/4; j++)
                *(float4*)&w[j*4] = *(const float4*)&Ws[kk][tx*TN + j*4];
            #pragma unroll
            for (int i = 0; i < TM; i++)
                #pragma unroll
                for (int j = 0; j < TN; j++) acc[i][j] += a[i] * w[j];
        }
        __syncthreads();
    }
    #pragma unroll
    for (int i = 0; i < TM; i++) {
        int m = m0 + ty*TM + i;
        if (m >= M) continue;
        #pragma unroll
        for (int j = 0; j < TN; j++) {
            int n = n0 + tx*TN + j;
            if (n >= N) continue;
            float v = acc[i][j];
            if (bias && ks == 0) v += bias[n];
            v *= alpha;
            float* dst = Cp + (ll)m * crs + (ll)n * ccs;
            if (ksplit == 1) *dst = v;
            else atomicAdd(dst, v);
        }
    }
}

/* ---------------- cosine scales per (b,r) --------------------------------- */
__global__ void scales_kernel(const float* __restrict__ z, const float* __restrict__ clt,
                              const float* __restrict__ p1, const float* __restrict__ p2,
                              float* __restrict__ s1o, float* __restrict__ s2o) {
    __shared__ float p1s[NC_], p2s[NC_], pn[2];
    int b = blockIdx.y;
    int r = blockIdx.x * 128 + threadIdx.x;
    int tid = threadIdx.x;
    for (int i = tid; i < NC_; i += 128) { p1s[i] = p1[i]; p2s[i] = p2[i]; }
    if (tid < 2) {
        const float* p = tid ? p2 : p1;
        float s = 0.f;
        for (int k = 0; k < NC_; k++) s += p[k]*p[k];
        pn[tid] = 1.0f / fmaxf(sqrtf(s), 1e-12f);
    }
    __syncthreads();
    const float* zb = z   + (ll)b * NC_ * R_ + r;
    const float* cb = clt + (ll)b * NC_ * R_ + r;
    float zz = 0.f, zp = 0.f, cc = 0.f, cp = 0.f;
    #pragma unroll 2
    for (int j = 0; j < NC_; j++) {
        float zv = zb[(ll)j * R_];
        float cv = cb[(ll)j * R_];
        zz += zv*zv; zp += zv*p1s[j];
        cc += cv*cv; cp += cv*p2s[j];
    }
    float s1 = zp * pn[0] / fmaxf(sqrtf(zz), 1e-12f);
    float s2 = cp * pn[1] / fmaxf(sqrtf(cc), 1e-12f);
    s1o[(ll)b*R_ + r] = fminf(fmaxf(s1, 0.f), 1.f);
    s2o[(ll)b*R_ + r] = fminf(fmaxf(s2, 0.f), 1.f);
}

/* ---------------- cxz = 0.5*(t1^T@(z*s1) + t2^T@(cl*s2)) ------------------
 * M=150(kp) N=16384(r) K=300(j). 256 threads, 64x64 tile, TM=TN=4.        */
__global__ void cxz_gemm(const float* __restrict__ z, const float* __restrict__ clt,
                         const float* __restrict__ t1, const float* __restrict__ t2,
                         const float* __restrict__ s1, const float* __restrict__ s2,
                         float* __restrict__ out) {
    constexpr int BK = 8;
    __shared__ __align__(16) float As[BK][68];
    __shared__ __align__(16) float Ws[BK][68];
    __shared__ float s1s[64], s2s[64];
    int b = blockIdx.z;
    int m0 = blockIdx.x * 64, n0 = blockIdx.y * 64;
    int tid = threadIdx.x, tx = tid % 16, ty = tid / 16;
    const float* zb = z   + (ll)b * NC_ * R_;
    const float* cb = clt + (ll)b * NC_ * R_;
    if (tid < 64) {
        s1s[tid] = s1[(ll)b * R_ + n0 + tid];
        s2s[tid] = s2[(ll)b * R_ + n0 + tid];
    }
    __syncthreads();
    float acc[4][4];
    #pragma unroll
    for (int i = 0; i < 4; i++)
        #pragma unroll
        for (int j = 0; j < 4; j++) acc[i][j] = 0.f;

    for (int k0 = 0; k0 < 2*NC_; k0 += BK) {
        /* A tile: As[kk][mm] = tcat[j=k0+kk, m0+mm] */
        for (int i = tid; i < 64 * BK; i += 256) {
            int mm = i % 64, kk = i / 64;
            int j = k0 + kk, m = m0 + mm;
            float v = 0.f;
            if (m < NC_) {
                if (j < NC_)        v = t1[j*NC_ + m];
                else if (j < 2*NC_) v = t2[(j-NC_)*NC_ + m];
            }
            As[kk][mm] = v;
        }
        /* W tile: scaled z / clt, float4 along r */
        for (int i = tid; i < 16 * BK; i += 256) {
            int q = i % 16, kk = i / 16;
            int j = k0 + kk, r = n0 + q*4;
            float4 v = make_float4(0.f,0.f,0.f,0.f);
            if (j < NC_) {
                v = *(const float4*)&zb[(ll)j * R_ + r];
                v.x *= s1s[q*4]; v.y *= s1s[q*4+1]; v.z *= s1s[q*4+2]; v.w *= s1s[q*4+3];
            } else if (j < 2*NC_) {
                v = *(const float4*)&cb[(ll)(j-NC_) * R_ + r];
                v.x *= s2s[q*4]; v.y *= s2s[q*4+1]; v.z *= s2s[q*4+2]; v.w *= s2s[q*4+3];
            }
            *(float4*)&Ws[kk][q*4] = v;
        }
        __syncthreads();
        #pragma unroll
        for (int kk = 0; kk < BK; kk++) {
            float a[4], w[4];
            *(float4*)a = *(const float4*)&As[kk][ty*4];
            *(float4*)w = *(const float4*)&Ws[kk][tx*4];
            #pragma unroll
            for (int i = 0; i < 4; i++)
                #pragma unroll
                for (int j = 0; j < 4; j++) acc[i][j] += a[i] * w[j];
        }
        __syncthreads();
    }
    #pragma unroll
    for (int i = 0; i < 4; i++) {
        int m = m0 + ty*4 + i;
        if (m >= NC_) continue;
        #pragma unroll
        for (int j = 0; j < 4; j++) {
            int r = n0 + tx*4 + j;
            out[((ll)(b*NC_ + m)) * R_ + r] = 0.5f * acc[i][j];
        }
    }
}

/* ---------------- softmax + raw copy -------------------------------------- */
__global__ void softmax_rows2(const float* __restrict__ cxz,
                              float* __restrict__ asn, float* __restrict__ soft) {
    int row = blockIdx.x;
    int b = row / 600; int rem = row - b * 600;
    int t = rem / NC_; int k = rem - t * NC_;
    const float* s = cxz + ((ll)(b * NC_ + k)) * R_ + (ll)t * N_;
    ll drow = ((ll)((b * T_ + t) * NC_ + k)) * N_;
    __shared__ float sh[8];
    int tid = threadIdx.x;
    float mx = -1e30f;
    for (int i = tid; i < N_; i += 256) mx = fmaxf(mx, s[i]);
    #pragma unroll
    for (int o = 16; o; o >>= 1) mx = fmaxf(mx, __shfl_xor_sync(0xffffffffu, mx, o));
    if ((tid & 31) == 0) sh[tid >> 5] = mx;
    __syncthreads();
    mx = fmaxf(fmaxf(fmaxf(sh[0],sh[1]),fmaxf(sh[2],sh[3])),
               fmaxf(fmaxf(sh[4],sh[5]),fmaxf(sh[6],sh[7])));
    __syncthreads();
    float sum = 0.f;
    for (int i = tid; i < N_; i += 256) sum += expf(s[i] - mx);
    sum = blockSum256(sum, sh);
    float inv = 1.0f / sum;
    for (int i = tid; i < N_; i += 256) {
        float v = s[i];
        asn[drow + i]  = v;
        soft[drow + i] = expf(v - mx) * inv;
    }
}

/* ---------------- gate + LayerNorm --------------------------------------- */
__global__ void gate_ln_kernel(const float* __restrict__ cen,
                               const float* __restrict__ nw, const float* __restrict__ nb,
                               const float* __restrict__ salpha, const float* __restrict__ sbeta,
                               float* __restrict__ cin_out) {
    int k = blockIdx.x, b = blockIdx.y, c = threadIdx.x;
    __shared__ float sh[8];
    float pv[4];
    #pragma unroll
    for (int t = 0; t < 4; t++)
        pv[t] = cen[(((ll)b*4 + t) * NC_ + k) * C_ + c];
    float last = pv[3];
    float ll2 = blockSum256(last*last, sh);
    float cin = last;
    float alpha = salpha[0], beta = sbeta[0];
    for (int t = 0; t < 3; t++) {
        float dt = blockSum256(last * pv[t], sh);
        float pp = blockSum256(pv[t] * pv[t], sh);
        float denom = fmaxf(sqrtf(ll2) * sqrtf(pp), 1e-8f);
        float gate = 1.0f / (1.0f + expf(-(beta + alpha * (dt / denom))));
        cin += gate * pv[t];
    }
    float m  = blockSum256(cin, sh) * (1.0f / C_);
    float dv = cin - m;
    float var = blockSum256(dv*dv, sh) * (1.0f / C_);
    cin_out[((ll)b*NC_ + k) * C_ + c] = dv * rsqrtf(var + 1e-5f) * nw[c] + nb[c];
}

/* ---------------- K/V projections ---------------------------------------- */
__global__ void kv_kernel(const float* __restrict__ cin,
                          const float* __restrict__ kw, const float* __restrict__ kb,
                          const float* __restrict__ vw, const float* __restrict__ vb,
                          float* __restrict__ ko, float* __restrict__ vo) {
    int row = blockIdx.x, c = threadIdx.x;
    __shared__ float ci[C_];
    ci[c] = cin[(ll)row * C_ + c];
    __syncthreads();
    float ka = kb[c], va = vb[c];
    const float* kwr = kw + (ll)c * C_;
    const float* vwr = vw + (ll)c * C_;
    #pragma unroll 4
    for (int j = 0; j < C_; j++) {
        float cv = ci[j];
        ka += cv * kwr[j];
        va += cv * vwr[j];
    }
    ko[(ll)row * C_ + c] = ka;
    vo[(ll)row * C_ + c] = va;
}

/* ---------------- fused attention (8 queries/block) ----------------------- */
__global__ void attn_kernel(const float* __restrict__ q, const float* __restrict__ ks,
                            const float* __restrict__ vs, float* __restrict__ o) {
    const int b = blockIdx.y;
    const int n0 = blockIdx.x * 8;
    __shared__ float qs[8][C_];
    __shared__ float P[8][8][152];
    int tid = threadIdx.x;
    for (int i = tid; i < 8*C_; i += 256)
        qs[i >> 8][i & 255] = q[((ll)b*N_ + n0 + (i >> 8)) * C_ + (i & 255)];
    __syncthreads();
    int h = tid >> 5, lane = tid & 31;
    float lg[8][5];
    #pragma unroll
    for (int g = 0; g < 8; g++)
        #pragma unroll
        for (int s = 0; s < 5; s++) lg[g][s] = -1e30f;
    #pragma unroll
    for (int s = 0; s < 5; s++) {
        int idx = lane + s*32;
        if (idx < NC_) {
            const float4* kp = reinterpret_cast<const float4*>(ks + ((ll)b*NC_ + idx)*C_ + h*32);
            float4 kk[8];
            #pragma unroll
            for (int u = 0; u < 8; u++) kk[u] = kp[u];
            #pragma unroll
            for (int g = 0; g < 8; g++) {
                const float* qb = &qs[g][h*32];
                float d = 0.f;
                #pragma unroll
                for (int u = 0; u < 8; u++)
                    d += kk[u].x*qb[u*4] + kk[u].y*qb[u*4+1] + kk[u].z*qb[u*4+2] + kk[u].w*qb[u*4+3];
                lg[g][s] = d;
            }
        }
    }
    float invg[8];
    #pragma unroll
    for (int g = 0; g < 8; g++) {
        float mx = -1e30f;
        #pragma unroll
        for (int s = 0; s < 5; s++) mx = fmaxf(mx, lg[g][s]);
        #pragma unroll
        for (int o2 = 16; o2; o2 >>= 1) mx = fmaxf(mx, __shfl_xor_sync(0xffffffffu, mx, o2));
        float sum = 0.f;
        #pragma unroll
        for (int s = 0; s < 5; s++) {
            int idx = lane + s*32;
            if (idx < NC_) {
                float e = expf(lg[g][s] - mx);
                P[h][g][idx] = e;
                sum += e;
            }
        }
        #pragma unroll
        for (int o2 = 16; o2; o2 >>= 1) sum += __shfl_xor_sync(0xffffffffu, sum, o2);
        invg[g] = 1.0f / sum;
    }
    __syncwarp();
    float og[8] = {0.f,0.f,0.f,0.f,0.f,0.f,0.f,0.f};
    for (int j = 0; j < NC_; j++) {
        float vv = vs[((ll)b*NC_ + j) * C_ + h*32 + lane];
        #pragma unroll
        for (int g = 0; g < 8; g++) og[g] += P[h][g][j] * vv;
    }
    #pragma unroll
    for (int g = 0; g < 8; g++)
        o[((ll)b*N_ + n0 + g) * C_ + h*32 + lane] = og[g] * invg[g];
}

/* ---------------- smem-tiled depthwise 3x3 conv + GELU -------------------- */
__global__ void conv_gelu2(const float* __restrict__ h,
                           const float* __restrict__ dww, const float* __restrict__ dwb,
                           float* __restrict__ out) {
    __shared__ float patch[10][10][64];
    int ch0 = blockIdx.x * 64;
    int tileid = blockIdx.y;
    int y0 = (tileid >> 3) * 8, x0 = (tileid & 7) * 8;
    int b = blockIdx.z;
    int tid = threadIdx.x;
    for (int i = tid; i < 6400; i += 256) {
        int c = i & 63, sp = i >> 6;
        int py = sp / 10, px = sp % 10;
        int yy = y0 + py - 1, xx = x0 + px - 1;
        float v = 0.f;
        if (yy >= 0 && yy < 64 && xx >= 0 && xx < 64)
            v = h[(((ll)b*N_) + (yy*64 + xx)) * HID_ + ch0 + c];
        patch[py][px][c] = v;
    }
    __syncthreads();
    int c = tid & 63, sub = tid >> 6;
    float w[9];
    #pragma unroll
    for (int i = 0; i < 9; i++) w[i] = dww[(ch0 + c)*9 + i];
    float bv = dwb[ch0 + c];
    for (int oy = sub; oy < 8; oy += 4) {
        #pragma unroll
        for (int ox = 0; ox < 8; ox++) {
            float a = bv;
            #pragma unroll
            for (int dy = 0; dy < 3; dy++)
                #pragma unroll
                for (int dx = 0; dx < 3; dx++)
                    a += patch[oy+dy][ox+dx][c] * w[dy*3+dx];
            float g = 0.5f * a * (1.0f + erff(a * 0.7071067811865475f));
            out[(((ll)b*N_) + ((y0+oy)*64 + x0+ox)) * HID_ + ch0 + c] = g;
        }
    }
}

/* ---------------- residual + LayerNorm ------------------------------------ */
__global__ void add_ln_kernel(const float* __restrict__ res, const float* __restrict__ val,
                              const float* __restrict__ nw, const float* __restrict__ nb,
                              float* __restrict__ dst) {
    ll row = blockIdx.x;
    int c = threadIdx.x;
    __shared__ float sh[8];
    float v = val[row * C_ + c];
    float m = blockSum256(v, sh) * (1.0f / C_);
    float d = v - m;
    float var = blockSum256(d*d, sh) * (1.0f / C_);
    dst[row * C_ + c] = res[row * C_ + c] + d * rsqrtf(var + 1e-5f) * nw[c] + nb[c];
}

/* ---------------- host launch --------------------------------------------- */
static float* symaddr(const void* sym) {
    void* p = nullptr;
    cudaGetSymbolAddress(&p, sym);
    return (float*)p;
}

extern "C" void kernel_launch(void* const* d_in, const int* in_sizes, int n_in,
                              void* d_out, int out_size) {
    const float* x    = (const float*)d_in[0];
    const float* z    = (const float*)d_in[1];
    const float* mem  = (const float*)d_in[2];
    const float* cw   = (const float*)d_in[3];
    const float* p1   = (const float*)d_in[4];
    const float* t1   = (const float*)d_in[5];
    const float* p2   = (const float*)d_in[6];
    const float* t2   = (const float*)d_in[7];
    const float* sal  = (const float*)d_in[8];
    const float* sbe  = (const float*)d_in[9];
    const float* qw   = (const float*)d_in[10];
    const float* qb   = (const float*)d_in[11];
    const float* kw   = (const float*)d_in[12];
    const float* kb   = (const float*)d_in[13];
    const float* vw   = (const float*)d_in[14];
    const float* vb   = (const float*)d_in[15];
    const float* pw   = (const float*)d_in[16];
    const float* pb   = (const float*)d_in[17];
    const float* nw   = (const float*)d_in[18];
    const float* nb   = (const float*)d_in[19];
    const float* f1w  = (const float*)d_in[20];
    const float* f1b  = (const float*)d_in[21];
    const float* dww  = (const float*)d_in[22];
    const float* dwb  = (const float*)d_in[23];
    const float* f2w  = (const float*)d_in[24];
    const float* f2b  = (const float*)d_in[25];

    float* out_main = (float*)d_out;
    float* out_cxz  = out_main + (ll)B_*N_*C_;
    float* out_asn  = out_cxz  + (ll)B_*NC_*R_;

    float* xf   = symaddr(g_xf);
    float* clt  = symaddr(g_clt);
    float* s1   = symaddr(g_s1);
    float* s2   = symaddr(g_s2);
    float* soft = symaddr(g_soft);
    float* cen  = symaddr(g_cen);
    float* cin  = symaddr(g_cin);
    float* ksc  = symaddr(g_k);
    float* vsc  = symaddr(g_v);
    float* qsc  = symaddr(g_q);
    float* atn  = symaddr(g_attn);
    float* tmp  = symaddr(g_tmp);
    float* out1 = symaddr(g_out1);
    float* h1   = symaddr(g_h1);
    float* hg   = symaddr(g_hg);

    /* 1. xf = concat(mem, x) */
    copy_xf_kernel<<<8192, 256>>>((const float4*)x, (const float4*)mem, (float4*)xf);

    /* 2. clt[b,k,r] = xf[b,r,:]·cw[k,:]  (transposed store, k-major) */
    gemm_t<128,32,8,4><<<dim3(R_/128, 5, B_), 128>>>(
        R_, NC_, C_, xf, C_, (ll)R_*C_, cw, C_, 0, 0,
        clt, 1, R_, (ll)NC_*R_, nullptr, 1.0f, 1);

    /* 3. cosine scales */
    scales_kernel<<<dim3(R_/128, B_), 128>>>(z, clt, p1, p2, s1, s2);

    /* 4. cluster_x_z (fused scaled GEMM) */
    cxz_gemm<<<dim3(3, R_/64, B_), 256>>>(z, clt, t1, t2, s1, s2, out_cxz);

    /* 5. softmax + assigned copy */
    softmax_rows2<<<B_*T_*NC_, 256>>>(out_cxz, out_asn, soft);

    /* 6. cen = soft @ xf  (split-K=8, atomic) */
    zero_kernel<<<(B_*T_*NC_*C_ + 255)/256, 256>>>(cen, B_*T_*NC_*C_);
    gemm_t<64,64,4,4><<<dim3(3, 4, B_*T_*8), 256>>>(
        NC_, C_, N_, soft, N_, (ll)NC_*N_, xf, C_, (ll)N_*C_, 1,
        cen, C_, 1, (ll)NC_*C_, nullptr, 1.0f, 8);

    /* 7. gate + LN */
    gate_ln_kernel<<<dim3(NC_, B_), 256>>>(cen, nw, nb, sal, sbe, cin);

    /* 8. k,v */
    kv_kernel<<<B_*NC_, 256>>>(cin, kw, kb, vw, vb, ksc, vsc);

    /* 9. q (split-K=2) */
    zero_kernel<<<(B_*N_*C_ + 255)/256, 256>>>(qsc, B_*N_*C_);
    gemm_t<128,128,8,8><<<dim3(64, 2, 2), 256>>>(
        B_*N_, C_, C_, x, C_, 0, qw, C_, 0, 0,
        qsc, C_, 1, 0, qb, 0.17677669529663687f, 2);

    /* 10. attention */
    attn_kernel<<<dim3(N_/8, B_), 256>>>(qsc, ksc, vsc, atn);

    /* 11. proj (split-K=2) */
    zero_kernel<<<(B_*N_*C_ + 255)/256, 256>>>(tmp, B_*N_*C_);
    gemm_t<128,128,8,8><<<dim3(64, 2, 2), 256>>>(
        B_*N_, C_, C_, atn, C_, 0, pw, C_, 0, 0,
        tmp, C_, 1, 0, pb, 1.0f, 2);

    /* 12. out1 = x + LN(proj) */
    add_ln_kernel<<<B_*N_, 256>>>(x, tmp, nw, nb, out1);

    /* 13. fc1 */
    gemm_t<128,128,8,8><<<dim3(64, 8, 1), 256>>>(
        B_*N_, HID_, C_, out1, C_, 0, f1w, C_, 0, 0,
        h1, HID_, 1, 0, f1b, 1.0f, 1);

    /* 14. depthwise conv + GELU (smem-tiled) */
    conv_gelu2<<<dim3(HID_/64, 64, B_), 256>>>(h1, dww, dwb, hg);

    /* 15. fc2 (split-K=2) */
    zero_kernel<<<(B_*N_*C_ + 255)/256, 256>>>(tmp, B_*N_*C_);
    gemm_t<128,128,8,8><<<dim3(64, 2, 2), 256>>>(
        B_*N_, C_, HID_, hg, HID_, 0, f2w, HID_, 0, 0,
        tmp, C_, 1, 0, f2b, 1.0f, 2);

    /* 16. out = out1 + LN(fc2) */
    add_ln_kernel<<<B_*N_, 256>>>(out1, tmp, nw, nb, out_main);
}